// round 1
// baseline (speedup 1.0000x reference)
#include <cuda_runtime.h>
#include <cuda_bf16.h>
#include <cstdint>

// Problem: out[i, f] = W[f, idx[i]] + b[f]
//   idx: [B*C*N] = 1,048,576 int32 in [0, 4096)
//   W:   [64, 4096] fp32 (row-major), b: [64] fp32
//   out: [B*C*N, 64] fp32  (268 MB) -- HBM-store-bound.
//
// Strategy:
//  1) Prologue kernel builds Wt[v][f] = W[f][v] + b[f] into a __device__
//     global (1 MB, L2-resident). Makes the gather contiguous and folds bias.
//  2) Gather kernel: 16 threads per index, each stores one float4.

#define VOCAB 4096
#define F_DIM 64
#define NUM_IDX (32 * 16 * 2048)

// Transposed, bias-fused table. 4096 * 64 floats = 1 MB.
__device__ float4 g_Wt[VOCAB * (F_DIM / 4)];

__global__ void build_table_kernel(const float* __restrict__ W,
                                   const float* __restrict__ b) {
    // One thread per output element of Wt (262144 elements).
    int t = blockIdx.x * blockDim.x + threadIdx.x;
    if (t >= VOCAB * F_DIM) return;
    int v = t >> 6;          // t / 64
    int f = t & 63;          // t % 64
    float val = W[f * VOCAB + v] + b[f];
    reinterpret_cast<float*>(g_Wt)[t] = val;
}

__global__ void gather_kernel(const int* __restrict__ idx,
                              float4* __restrict__ out) {
    // Each thread moves one float4; 16 threads cooperate on one index.
    // total threads = NUM_IDX * 16 = 16,777,216
    int t = blockIdx.x * blockDim.x + threadIdx.x;
    int i = t >> 4;          // index id
    int f4 = t & 15;         // which float4 within the 64-float row
    int v = __ldg(&idx[i]);
    out[t] = g_Wt[v * 16 + f4];
}

extern "C" void kernel_launch(void* const* d_in, const int* in_sizes, int n_in,
                              void* d_out, int out_size) {
    const int* x = (const int*)d_in[0];           // [B,C,1,N] int32 -> flat [B*C*N]
    const float* W = (const float*)d_in[1];       // [64, 4096]
    const float* b = (const float*)d_in[2];       // [64]
    float4* out = (float4*)d_out;

    // 1) Build bias-fused transposed table.
    {
        int total = VOCAB * F_DIM;
        int threads = 256;
        int blocks = (total + threads - 1) / threads;
        build_table_kernel<<<blocks, threads>>>(W, b);
    }

    // 2) Gather: 16M float4 stores.
    {
        long long total = (long long)NUM_IDX * 16;
        int threads = 256;
        long long blocks = (total + threads - 1) / threads;
        gather_kernel<<<(unsigned)blocks, threads>>>(x, out);
    }
}

// round 2
// speedup vs baseline: 1.5791x; 1.5791x over previous
#include <cuda_runtime.h>
#include <cuda_bf16.h>
#include <cstdint>

// out[i, f] = W[f, idx[i]] + b[f]
//   idx: [1,048,576] int32 in [0,4096); W: [64,4096] fp32; b: [64] fp32
//   out: [1M, 64] fp32 (268 MB). HBM-store-bound in the limit; R1 showed
//   latency-bound (MLP=1). R2: unroll x4 for MLP, streaming stores.

#define VOCAB 4096
#define F_DIM 64
#define NUM_IDX (32 * 16 * 2048)
#define TOTAL_F4 ((long long)NUM_IDX * 16)   // 16,777,216 float4 stores
#define UNROLL 4

// Transposed, bias-fused table: Wt[v][f] = W[f][v] + b[f]. 1 MB, L2-resident.
__device__ float4 g_Wt[VOCAB * (F_DIM / 4)];

// ---------------------------------------------------------------------------
// Prologue: tiled transpose with bias fusion. Coalesced on both sides.
// W is [F_DIM=64, VOCAB=4096]. Tile 32x32. grid = (4096/32, 64/32) = (128, 2).
// ---------------------------------------------------------------------------
__global__ void build_table_kernel(const float* __restrict__ W,
                                   const float* __restrict__ b) {
    __shared__ float tile[32][33];   // +1 pad: conflict-free transpose
    int vbase = blockIdx.x * 32;
    int fbase = blockIdx.y * 32;

    // Load: threads contiguous along v (coalesced reads of W rows).
    // blockDim = (32, 8): each thread loads 4 rows.
    #pragma unroll
    for (int r = 0; r < 4; r++) {
        int f = threadIdx.y + r * 8;           // 0..31 within tile
        int v = threadIdx.x;                   // 0..31 within tile
        tile[f][v] = W[(fbase + f) * VOCAB + (vbase + v)];
    }
    __syncthreads();

    // Store: threads contiguous along f (coalesced writes of Wt rows).
    float* Wt = reinterpret_cast<float*>(g_Wt);
    #pragma unroll
    for (int r = 0; r < 4; r++) {
        int v = threadIdx.y + r * 8;           // 0..31 within tile
        int f = threadIdx.x;                   // 0..31 within tile
        Wt[(long long)(vbase + v) * F_DIM + (fbase + f)] =
            tile[f][v] + b[fbase + f];
    }
}

// ---------------------------------------------------------------------------
// Gather: 16 threads per index, each moves one float4. Unrolled x4 across
// chunks of size G so all loads in an iteration are independent (MLP=4+4)
// while stores remain fully coalesced within each warp.
// ---------------------------------------------------------------------------
__global__ void gather_kernel(const int* __restrict__ idx,
                              float4* __restrict__ out) {
    const long long G = TOTAL_F4 / UNROLL;     // 4,194,304
    long long t = (long long)blockIdx.x * blockDim.x + threadIdx.x;

    // 4 independent idx loads (L1-broadcast hits for 15/16 threads)
    int v0 = __ldg(&idx[(t          ) >> 4]);
    int v1 = __ldg(&idx[(t +     G  ) >> 4]);
    int v2 = __ldg(&idx[(t + 2 * G  ) >> 4]);
    int v3 = __ldg(&idx[(t + 3 * G  ) >> 4]);

    int f4 = (int)(t & 15);

    // 4 independent table loads (L2 hits, latency overlapped)
    float4 r0 = __ldg(&g_Wt[v0 * 16 + f4]);
    float4 r1 = __ldg(&g_Wt[v1 * 16 + f4]);
    float4 r2 = __ldg(&g_Wt[v2 * 16 + f4]);
    float4 r3 = __ldg(&g_Wt[v3 * 16 + f4]);

    // Streaming stores: output is write-once, don't pollute L2.
    __stcs(&out[t          ], r0);
    __stcs(&out[t +     G  ], r1);
    __stcs(&out[t + 2 * G  ], r2);
    __stcs(&out[t + 3 * G  ], r3);
}

extern "C" void kernel_launch(void* const* d_in, const int* in_sizes, int n_in,
                              void* d_out, int out_size) {
    const int* x = (const int*)d_in[0];
    const float* W = (const float*)d_in[1];
    const float* b = (const float*)d_in[2];
    float4* out = (float4*)d_out;

    {
        dim3 threads(32, 8);
        dim3 blocks(VOCAB / 32, F_DIM / 32);
        build_table_kernel<<<blocks, threads>>>(W, b);
    }
    {
        long long total_threads = TOTAL_F4 / UNROLL;   // 4,194,304
        int threads = 256;
        int blocks = (int)(total_threads / threads);   // 16384
        gather_kernel<<<blocks, threads>>>(x, out);
    }
}